// round 14
// baseline (speedup 1.0000x reference)
#include <cuda_runtime.h>
#include <cuda_fp16.h>
#include <math.h>
#include <stdint.h>

#define NTOK 2048
#define DMOD 512
#define NH 8
#define HDIM 64
#define NBINS 16

// ---------------------------------------------------------------------------
// Scratch (no cudaMalloc). Only referenced from DEVICE code.
// ---------------------------------------------------------------------------
__device__ __half g_Xh[NTOK * DMOD], g_Xl[NTOK * DMOD];    // split x (fp16 hi/lo)
__device__ __half g_Wt[1536 * 512];                        // (Wq|Wk|Wv)^T fp16
__device__ __half g_Wot[512 * 512];                        // Wo^T fp16
__device__ __half g_AOh[NTOK * DMOD], g_AOl[NTOK * DMOD];  // attn out split fp16
__device__ __half g_Qf[NTOK * DMOD];                       // [h][tok][64] fp16
__device__ __half g_Kf[NTOK * DMOD];                       // [h][tok][64] fp16
__device__ __half g_Vf[NTOK * DMOD];                       // [h][tok][64] fp16
__device__ uint8_t g_bins[NTOK * NTOK];

#define LOG2E 1.4426950408889634f

// ---------------------------------------------------------------------------
// mma.sync / cp.async / ldmatrix helpers
// ---------------------------------------------------------------------------
__device__ __forceinline__ void mma_fp16(float* c, const uint32_t* a,
                                         uint32_t b0, uint32_t b1) {
    asm volatile(
        "mma.sync.aligned.m16n8k16.row.col.f32.f16.f16.f32 "
        "{%0,%1,%2,%3},{%4,%5,%6,%7},{%8,%9},{%0,%1,%2,%3};"
        : "+f"(c[0]), "+f"(c[1]), "+f"(c[2]), "+f"(c[3])
        : "r"(a[0]), "r"(a[1]), "r"(a[2]), "r"(a[3]), "r"(b0), "r"(b1));
}
__device__ __forceinline__ void ldsm4(uint32_t& r0, uint32_t& r1,
                                      uint32_t& r2, uint32_t& r3, uint32_t addr) {
    asm volatile("ldmatrix.sync.aligned.m8n8.x4.shared.b16 {%0,%1,%2,%3}, [%4];"
                 : "=r"(r0), "=r"(r1), "=r"(r2), "=r"(r3) : "r"(addr));
}
__device__ __forceinline__ void ldsm4t(uint32_t& r0, uint32_t& r1,
                                       uint32_t& r2, uint32_t& r3, uint32_t addr) {
    asm volatile("ldmatrix.sync.aligned.m8n8.x4.trans.shared.b16 {%0,%1,%2,%3}, [%4];"
                 : "=r"(r0), "=r"(r1), "=r"(r2), "=r"(r3) : "r"(addr));
}
__device__ __forceinline__ void cp16(uint32_t dst, const void* src) {
    asm volatile("cp.async.cg.shared.global [%0], [%1], 16;" :: "r"(dst), "l"(src));
}
__device__ __forceinline__ uint32_t smem_u32(const void* p) {
    uint32_t a;
    asm("{ .reg .u64 t; cvta.to.shared.u64 t, %1; cvt.u32.u64 %0, t; }"
        : "=r"(a) : "l"(p));
    return a;
}
__device__ __forceinline__ uint32_t pack2h(float a, float b) {
    __half2 t;
    t.x = __float2half_rn(a);
    t.y = __float2half_rn(b);
    return *(uint32_t*)&t;
}
__device__ __forceinline__ float fast_exp2(float x) {
    float r;
    asm("ex2.approx.ftz.f32 %0, %1;" : "=f"(r) : "f"(x));
    return r;
}

// ---------------------------------------------------------------------------
// 2-term split-fp16 tensor-core GEMM, 32x128 (MxN) tiles for full-chip occ.
// 8 warps = 2 M-groups x 4 N-quarters (32 cols).
// mode 0: QKV (grid 12x64 = 768 CTAs); mode 1: outproj (grid 4x64 = 256 CTAs).
// ---------------------------------------------------------------------------
#define GPIT 80
#define GAH 0
#define GAL 2560
#define GB  5120
#define GSTAGE 15360
#define GEMM_SMEM (2 * GSTAGE)

__global__ __launch_bounds__(256, 2) void gemm_mma_kernel(
    int mode, const float* __restrict__ b0p, const float* __restrict__ b1p,
    const float* __restrict__ b2p, float* __restrict__ C_ext)
{
    extern __shared__ char smem[];
    const __half *Ah, *Al, *Bt;
    if (mode == 0) {
        Ah = g_Xh;  Al = g_Xl;  Bt = g_Wt;
    } else {
        Ah = g_AOh; Al = g_AOl; Bt = g_Wot;
    }

    const int tid = threadIdx.x;
    const int w = tid >> 5, l = tid & 31, g = l >> 2, t = l & 3;
    const int q4 = l >> 3, r8 = l & 7;
    const int wq = w & 1;          // M row-group (2 x 16 rows)
    const int wn = w >> 1;         // N quarter (4 x 32 cols)
    const int n0 = blockIdx.x * 128;
    const int mb = blockIdx.y * 32;
    const uint32_t sbase = smem_u32(smem);

    const uint32_t aln = (uint32_t)(wq * 16 + 8 * (q4 & 1) + r8) * GPIT + 16 * (q4 >> 1);
    const uint32_t bln = (uint32_t)(wn * 32 + 8 * (q4 >> 1) + r8) * GPIT + 16 * (q4 & 1);

    auto load = [&](int kc, int st) {
        uint32_t b = sbase + st * GSTAGE;
        {   // A hi/lo: 32 rows x 64B; 128 slots each, tid>>7 selects hi/lo
            int slot = tid & 127;
            int r = slot >> 2, c = slot & 3;
            uint32_t so = r * GPIT + c * 16;
            size_t ga = ((size_t)(mb + r) * 512 + kc * 32) * 2 + c * 16;
            if (tid < 128) cp16(b + GAH + so, (const char*)Ah + ga);
            else           cp16(b + GAL + so, (const char*)Al + ga);
        }
        #pragma unroll
        for (int p = 0; p < 2; p++) {   // B: 128 rows x 64B
            int i = tid + p * 256;
            int r = i >> 2, c = i & 3;
            size_t gb = ((size_t)(n0 + r) * 512 + kc * 32) * 2 + c * 16;
            cp16(b + GB + r * GPIT + c * 16, (const char*)Bt + gb);
        }
        asm volatile("cp.async.commit_group;" ::: "memory");
    };

    float acc[4][4];
    #pragma unroll
    for (int j = 0; j < 4; j++)
        #pragma unroll
        for (int i = 0; i < 4; i++) acc[j][i] = 0.0f;

    load(0, 0);
    for (int kc = 0; kc < 16; kc++) {
        if (kc + 1 < 16) {
            load(kc + 1, (kc + 1) & 1);
            asm volatile("cp.async.wait_group 1;" ::: "memory");
        } else {
            asm volatile("cp.async.wait_group 0;" ::: "memory");
        }
        __syncthreads();
        const uint32_t sb = sbase + (kc & 1) * GSTAGE;

        #pragma unroll
        for (int kk = 0; kk < 2; kk++) {
            uint32_t ah[4], al[4];
            ldsm4(ah[0], ah[1], ah[2], ah[3], sb + GAH + aln + kk * 32);
            ldsm4(al[0], al[1], al[2], al[3], sb + GAL + aln + kk * 32);
            uint32_t b0[2], b1[2], b2[2], b3[2];
            #pragma unroll
            for (int jp = 0; jp < 2; jp++)
                ldsm4(b0[jp], b1[jp], b2[jp], b3[jp],
                      sb + GB + bln + (uint32_t)jp * (16 * GPIT) + kk * 32);
            // hi-term MMAs first (independent), then lo-term
            #pragma unroll
            for (int jp = 0; jp < 2; jp++) {
                mma_fp16(acc[2 * jp],     ah, b0[jp], b1[jp]);
                mma_fp16(acc[2 * jp + 1], ah, b2[jp], b3[jp]);
            }
            #pragma unroll
            for (int jp = 0; jp < 2; jp++) {
                mma_fp16(acc[2 * jp],     al, b0[jp], b1[jp]);
                mma_fp16(acc[2 * jp + 1], al, b2[jp], b3[jp]);
            }
        }
        __syncthreads();
    }

    const int r0 = mb + wq * 16 + g, r1 = r0 + 8;
    if (mode == 1) {
        #pragma unroll
        for (int j = 0; j < 4; j++) {
            int col = n0 + wn * 32 + 8 * j + 2 * t;
            float bv0 = b0p[col], bv1 = b0p[col + 1];
            *(float2*)&C_ext[(size_t)r0 * 512 + col] =
                make_float2(acc[j][0] + bv0, acc[j][1] + bv1);
            *(float2*)&C_ext[(size_t)r1 * 512 + col] =
                make_float2(acc[j][2] + bv0, acc[j][3] + bv1);
        }
    } else {
        const float QS = 0.125f * LOG2E;
        #pragma unroll
        for (int j = 0; j < 4; j++) {
            int col = n0 + wn * 32 + 8 * j + 2 * t;
            const float* bp = (col < 512) ? b0p : (col < 1024 ? b1p : b2p);
            int cc = col & 511;
            float bv0 = bp[cc], bv1 = bp[cc + 1];
            float v00 = acc[j][0] + bv0, v01 = acc[j][1] + bv1;
            float v10 = acc[j][2] + bv0, v11 = acc[j][3] + bv1;
            int h = cc >> 6, d = cc & 63;
            size_t d0 = ((size_t)h * NTOK + r0) * HDIM + d;
            size_t d1 = ((size_t)h * NTOK + r1) * HDIM + d;
            if (col < 512) {
                *(uint32_t*)&g_Qf[d0] = pack2h(v00 * QS, v01 * QS);
                *(uint32_t*)&g_Qf[d1] = pack2h(v10 * QS, v11 * QS);
            } else if (col < 1024) {
                *(uint32_t*)&g_Kf[d0] = pack2h(v00, v01);
                *(uint32_t*)&g_Kf[d1] = pack2h(v10, v11);
            } else {
                *(uint32_t*)&g_Vf[d0] = pack2h(v00, v01);
                *(uint32_t*)&g_Vf[d1] = pack2h(v10, v11);
            }
        }
    }
}

// ---------------------------------------------------------------------------
// Fused input prep:
//   blocks [0,4096): z bins | [4096,5120): W transpose (fp16) | [5120,9216): x split fp16
// ---------------------------------------------------------------------------
__device__ __forceinline__ uint8_t bin_of(float z) {
    int b = (int)floorf(z / 5.0f * 16.0f);
    return (uint8_t)max(0, min(NBINS - 1, b));
}

__global__ __launch_bounds__(256) void prep_in_kernel(
    const float* __restrict__ x, const float* __restrict__ zmat,
    const float* __restrict__ Wq, const float* __restrict__ Wk,
    const float* __restrict__ Wv, const float* __restrict__ Wo)
{
    int bx = blockIdx.x;
    int tid = threadIdx.x;
    if (bx < 4096) {
        size_t i = (size_t)bx * 256 + tid;
        float4 z = *(const float4*)(zmat + i * 4);
        uchar4 b;
        b.x = bin_of(z.x); b.y = bin_of(z.y); b.z = bin_of(z.z); b.w = bin_of(z.w);
        *(uchar4*)(g_bins + i * 4) = b;
    } else if (bx < 5120) {
        __shared__ float ts[32][33];
        int bb = bx - 4096;
        int zb = bb >> 8, rem = bb & 255;
        int k0 = (rem & 15) * 32;
        int n0 = (rem >> 4) * 32;
        const float* src;
        __half* dh;
        int nbase;
        if (zb == 0)      { src = Wq; dh = g_Wt;  nbase = 0; }
        else if (zb == 1) { src = Wk; dh = g_Wt;  nbase = 512; }
        else if (zb == 2) { src = Wv; dh = g_Wt;  nbase = 1024; }
        else              { src = Wo; dh = g_Wot; nbase = 0; }
        int tx = tid & 31, ty = tid >> 5;
        #pragma unroll
        for (int i = 0; i < 4; i++) {
            int r = ty + i * 8;
            ts[r][tx] = src[(size_t)(k0 + r) * 512 + n0 + tx];
        }
        __syncthreads();
        #pragma unroll
        for (int i = 0; i < 4; i++) {
            int nn = ty + i * 8;
            dh[(size_t)(nbase + n0 + nn) * 512 + k0 + tx] = __float2half_rn(ts[tx][nn]);
        }
    } else {
        int i = (bx - 5120) * 256 + tid;
        float v = x[i];
        __half h = __float2half_rn(v);
        g_Xh[i] = h;
        g_Xl[i] = __float2half_rn(v - __half2float(h));
    }
}

// ---------------------------------------------------------------------------
// fp16 mma.sync flash attention (validated R13): 128 q-rows, 8 warps.
// K via ldmatrix; V via ldmatrix.trans; l via FADDs.
// ---------------------------------------------------------------------------
#define KP 144
#define VP 144
#define BP 144
#define KF_O 0
#define VT_O 18432
#define BN_O 36864
#define STAGE 55296
#define ATTN_SMEM (2 * STAGE)

__global__ __launch_bounds__(256, 1) void attn_mma_kernel(const float* __restrict__ ztab)
{
    extern __shared__ char smem[];
    __shared__ float zt[NBINS];

    const int tid = threadIdx.x;
    const int w   = tid >> 5;
    const int l   = tid & 31;
    const int g   = l >> 2;
    const int t   = l & 3;
    const int q4  = l >> 3, r8 = l & 7;
    const int h   = blockIdx.y;
    const int q0  = blockIdx.x * 128;
    const int m0  = w * 16;

    if (tid < NBINS) zt[tid] = ztab[tid * NH + h] * LOG2E;

    const uint32_t sbase = smem_u32(smem);

    const uint32_t kln = (uint32_t)(8 * (q4 >> 1) + r8) * KP + 16 * (q4 & 1);
    const uint32_t vln = (uint32_t)(8 * (q4 & 1) + r8) * VP + 16 * (q4 >> 1);

    auto load_tile = [&](int kt, int stage) {
        uint32_t base = sbase + stage * STAGE;
        #pragma unroll
        for (int p = 0; p < 4; p++) {
            int i = tid + p * 256;
            int r = i >> 3, c = i & 7;
            cp16(base + KF_O + r * KP + c * 16,
                 (const char*)g_Kf + (((size_t)h * NTOK + kt * 128 + r) * HDIM) * 2 + c * 16);
        }
        #pragma unroll
        for (int p = 0; p < 4; p++) {
            int i = tid + p * 256;
            int r = i >> 3, c = i & 7;
            cp16(base + VT_O + r * VP + c * 16,
                 (const char*)g_Vf + (((size_t)h * NTOK + kt * 128 + r) * HDIM) * 2 + c * 16);
        }
        #pragma unroll
        for (int p = 0; p < 4; p++) {
            int i = tid + p * 256;
            int r = i >> 3, c = i & 7;
            cp16(base + BN_O + r * BP + c * 16,
                 g_bins + (size_t)(q0 + r) * NTOK + kt * 128 + c * 16);
        }
        asm volatile("cp.async.commit_group;" ::: "memory");
    };

    load_tile(0, 0);

    uint32_t qf[4][4];
    {
        const uint16_t* qb = (const uint16_t*)g_Qf + ((size_t)h * NTOK + q0 + m0) * HDIM;
        #pragma unroll
        for (int kk = 0; kk < 4; kk++) {
            int c0 = 16 * kk + 2 * t;
            qf[kk][0] = *(const uint32_t*)(qb + (size_t)g * HDIM + c0);
            qf[kk][1] = *(const uint32_t*)(qb + (size_t)(g + 8) * HDIM + c0);
            qf[kk][2] = *(const uint32_t*)(qb + (size_t)g * HDIM + c0 + 8);
            qf[kk][3] = *(const uint32_t*)(qb + (size_t)(g + 8) * HDIM + c0 + 8);
        }
    }

    float oc[8][4];
    #pragma unroll
    for (int j = 0; j < 8; j++)
        #pragma unroll
        for (int i = 0; i < 4; i++) oc[j][i] = 0.0f;
    float l0 = 0.0f, l1 = 0.0f;

    for (int kt = 0; kt < NTOK / 128; kt++) {
        if (kt + 1 < NTOK / 128) {
            load_tile(kt + 1, (kt + 1) & 1);
            asm volatile("cp.async.wait_group 1;" ::: "memory");
        } else {
            asm volatile("cp.async.wait_group 0;" ::: "memory");
        }
        __syncthreads();

        const uint32_t sb = sbase + (kt & 1) * STAGE;
        const char* BN = smem + (kt & 1) * STAGE + BN_O;

        float sc[16][4];
        #pragma unroll
        for (int j = 0; j < 16; j++)
            #pragma unroll
            for (int i = 0; i < 4; i++) sc[j][i] = 0.0f;

        #pragma unroll
        for (int kk = 0; kk < 4; kk++) {
            #pragma unroll
            for (int jp = 0; jp < 8; jp++) {
                uint32_t b0, b1, b2, b3;
                ldsm4(b0, b1, b2, b3, sb + KF_O + kln + (uint32_t)jp * (16 * KP) + kk * 32);
                mma_fp16(sc[2 * jp],     qf[kk], b0, b1);
                mma_fp16(sc[2 * jp + 1], qf[kk], b2, b3);
            }
        }

        uint32_t ph[8][4];
        #pragma unroll
        for (int j = 0; j < 16; j++) {
            int col = 8 * j + 2 * t;
            uint16_t bA = *(const uint16_t*)(BN + (uint32_t)(m0 + g) * BP + col);
            uint16_t bB = *(const uint16_t*)(BN + (uint32_t)(m0 + g + 8) * BP + col);
            float p0 = fast_exp2(sc[j][0] + zt[bA & 0xFF]);
            float p1 = fast_exp2(sc[j][1] + zt[bA >> 8]);
            float p2 = fast_exp2(sc[j][2] + zt[bB & 0xFF]);
            float p3 = fast_exp2(sc[j][3] + zt[bB >> 8]);
            l0 += p0 + p1;
            l1 += p2 + p3;
            int kp = j >> 1, hf = (j & 1) * 2;
            ph[kp][hf + 0] = pack2h(p0, p1);
            ph[kp][hf + 1] = pack2h(p2, p3);
        }

        #pragma unroll
        for (int kp = 0; kp < 8; kp++) {
            #pragma unroll
            for (int jjp = 0; jjp < 2; jjp++) {
                uint32_t v0, v1, v2, v3;
                ldsm4t(v0, v1, v2, v3,
                       sb + VT_O + vln + (uint32_t)kp * (16 * VP) + jjp * 32);
                mma_fp16(oc[4 * jjp + 0], ph[kp], v0, v1);
                mma_fp16(oc[4 * jjp + 1], ph[kp], v2, v3);
            }
            #pragma unroll
            for (int jjp = 0; jjp < 2; jjp++) {
                uint32_t v0, v1, v2, v3;
                ldsm4t(v0, v1, v2, v3,
                       sb + VT_O + vln + (uint32_t)kp * (16 * VP) + 64 + jjp * 32);
                mma_fp16(oc[4 * jjp + 2], ph[kp], v0, v1);
                mma_fp16(oc[4 * jjp + 3], ph[kp], v2, v3);
            }
        }
        __syncthreads();
    }

    l0 += __shfl_xor_sync(0xffffffffu, l0, 1);
    l0 += __shfl_xor_sync(0xffffffffu, l0, 2);
    l1 += __shfl_xor_sync(0xffffffffu, l1, 1);
    l1 += __shfl_xor_sync(0xffffffffu, l1, 2);
    float inv0 = 1.0f / l0, inv1 = 1.0f / l1;

    const int dmap[8] = {0, 8, 32, 40, 16, 24, 48, 56};

    int r0 = q0 + m0 + g, r1 = r0 + 8;
    #pragma unroll
    for (int jj = 0; jj < 8; jj++) {
        int col = h * HDIM + dmap[jj] + 2 * t;
        float v00 = oc[jj][0] * inv0, v01 = oc[jj][1] * inv0;
        float v10 = oc[jj][2] * inv1, v11 = oc[jj][3] * inv1;
        __half h00 = __float2half_rn(v00);
        __half h01 = __float2half_rn(v01);
        __half h10 = __float2half_rn(v10);
        __half h11 = __float2half_rn(v11);
        __half2 u0; u0.x = h00; u0.y = h01;
        __half2 u1; u1.x = h10; u1.y = h11;
        *(uint32_t*)&g_AOh[(size_t)r0 * DMOD + col] = *(uint32_t*)&u0;
        *(uint32_t*)&g_AOh[(size_t)r1 * DMOD + col] = *(uint32_t*)&u1;
        *(uint32_t*)&g_AOl[(size_t)r0 * DMOD + col] =
            pack2h(v00 - __half2float(h00), v01 - __half2float(h01));
        *(uint32_t*)&g_AOl[(size_t)r1 * DMOD + col] =
            pack2h(v10 - __half2float(h10), v11 - __half2float(h11));
    }
}

// ---------------------------------------------------------------------------

extern "C" void kernel_launch(void* const* d_in, const int* in_sizes, int n_in,
                              void* d_out, int out_size)
{
    const float* x  = (const float*)d_in[0];
    const float* z  = (const float*)d_in[1];
    const float* Wq = (const float*)d_in[2];
    const float* bq = (const float*)d_in[3];
    const float* Wk = (const float*)d_in[4];
    const float* bk = (const float*)d_in[5];
    const float* Wv = (const float*)d_in[6];
    const float* bv = (const float*)d_in[7];
    const float* Wo = (const float*)d_in[8];
    const float* bo = (const float*)d_in[9];
    const float* zt = (const float*)d_in[10];
    float* out = (float*)d_out;

    cudaFuncSetAttribute(attn_mma_kernel,
                         cudaFuncAttributeMaxDynamicSharedMemorySize, ATTN_SMEM);
    cudaFuncSetAttribute(gemm_mma_kernel,
                         cudaFuncAttributeMaxDynamicSharedMemorySize, GEMM_SMEM);

    // fused prep: bins + W transpose (fp16) + x split (fp16)
    prep_in_kernel<<<9216, 256>>>(x, z, Wq, Wk, Wv, Wo);

    // fused QKV projection (2-term fp16, 32x128 tiles -> 768 CTAs)
    gemm_mma_kernel<<<dim3(12, 64), 256, GEMM_SMEM>>>(0, bq, bk, bv, nullptr);

    // attention (V via ldmatrix.trans)
    attn_mma_kernel<<<dim3(NTOK / 128, NH), 256, ATTN_SMEM>>>(zt);

    // output projection (32x128 tiles -> 256 CTAs)
    gemm_mma_kernel<<<dim3(4, 64), 256, GEMM_SMEM>>>(1, bo, nullptr, nullptr, out);
}

// round 15
// speedup vs baseline: 1.0695x; 1.0695x over previous
#include <cuda_runtime.h>
#include <cuda_fp16.h>
#include <math.h>
#include <stdint.h>

#define NTOK 2048
#define DMOD 512
#define NH 8
#define HDIM 64
#define NBINS 16

// ---------------------------------------------------------------------------
// Scratch (no cudaMalloc). Only referenced from DEVICE code.
// ---------------------------------------------------------------------------
__device__ __half g_Xh[NTOK * DMOD], g_Xl[NTOK * DMOD];    // split x (fp16 hi/lo)
__device__ __half g_Wt[1536 * 512];                        // (Wq|Wk|Wv)^T fp16
__device__ __half g_Wot[512 * 512];                        // Wo^T fp16
__device__ __half g_AOh[NTOK * DMOD], g_AOl[NTOK * DMOD];  // attn out split fp16
__device__ __half g_Qf[NTOK * DMOD];                       // [h][tok][64] fp16
__device__ __half g_Kf[NTOK * DMOD];                       // [h][tok][64] fp16
__device__ __half g_Vf[NTOK * DMOD];                       // [h][tok][64] fp16
__device__ uint8_t g_bins[NTOK * NTOK];

#define LOG2E 1.4426950408889634f

// ---------------------------------------------------------------------------
// mma.sync / cp.async / ldmatrix helpers
// ---------------------------------------------------------------------------
__device__ __forceinline__ void mma_fp16(float* c, const uint32_t* a,
                                         uint32_t b0, uint32_t b1) {
    asm volatile(
        "mma.sync.aligned.m16n8k16.row.col.f32.f16.f16.f32 "
        "{%0,%1,%2,%3},{%4,%5,%6,%7},{%8,%9},{%0,%1,%2,%3};"
        : "+f"(c[0]), "+f"(c[1]), "+f"(c[2]), "+f"(c[3])
        : "r"(a[0]), "r"(a[1]), "r"(a[2]), "r"(a[3]), "r"(b0), "r"(b1));
}
__device__ __forceinline__ void ldsm4(uint32_t& r0, uint32_t& r1,
                                      uint32_t& r2, uint32_t& r3, uint32_t addr) {
    asm volatile("ldmatrix.sync.aligned.m8n8.x4.shared.b16 {%0,%1,%2,%3}, [%4];"
                 : "=r"(r0), "=r"(r1), "=r"(r2), "=r"(r3) : "r"(addr));
}
__device__ __forceinline__ void ldsm4t(uint32_t& r0, uint32_t& r1,
                                       uint32_t& r2, uint32_t& r3, uint32_t addr) {
    asm volatile("ldmatrix.sync.aligned.m8n8.x4.trans.shared.b16 {%0,%1,%2,%3}, [%4];"
                 : "=r"(r0), "=r"(r1), "=r"(r2), "=r"(r3) : "r"(addr));
}
__device__ __forceinline__ void cp16(uint32_t dst, const void* src) {
    asm volatile("cp.async.cg.shared.global [%0], [%1], 16;" :: "r"(dst), "l"(src));
}
__device__ __forceinline__ uint32_t smem_u32(const void* p) {
    uint32_t a;
    asm("{ .reg .u64 t; cvta.to.shared.u64 t, %1; cvt.u32.u64 %0, t; }"
        : "=r"(a) : "l"(p));
    return a;
}
__device__ __forceinline__ uint32_t pack2h(float a, float b) {
    __half2 t;
    t.x = __float2half_rn(a);
    t.y = __float2half_rn(b);
    return *(uint32_t*)&t;
}
__device__ __forceinline__ float fast_exp2(float x) {
    float r;
    asm("ex2.approx.ftz.f32 %0, %1;" : "=f"(r) : "f"(x));
    return r;
}

// ---------------------------------------------------------------------------
// 2-term split-fp16 tensor-core GEMM, 32x128 tiles, k-chunk 64 (8 outer iters,
// 32-MMA bursts per sync window). 8 warps = 2 M-groups x 4 N-quarters.
// mode 0: QKV (grid 12x64 = 768 CTAs); mode 1: outproj (grid 4x64 = 256 CTAs).
// ---------------------------------------------------------------------------
#define GPIT 144
#define GAH 0
#define GAL 4608
#define GB  9216
#define GSTAGE 27648
#define GEMM_SMEM (2 * GSTAGE)

__global__ __launch_bounds__(256, 2) void gemm_mma_kernel(
    int mode, const float* __restrict__ b0p, const float* __restrict__ b1p,
    const float* __restrict__ b2p, float* __restrict__ C_ext)
{
    extern __shared__ char smem[];
    const __half *Ah, *Al, *Bt;
    if (mode == 0) {
        Ah = g_Xh;  Al = g_Xl;  Bt = g_Wt;
    } else {
        Ah = g_AOh; Al = g_AOl; Bt = g_Wot;
    }

    const int tid = threadIdx.x;
    const int w = tid >> 5, l = tid & 31, g = l >> 2, t = l & 3;
    const int q4 = l >> 3, r8 = l & 7;
    const int wq = w & 1;          // M row-group (2 x 16 rows)
    const int wn = w >> 1;         // N quarter (4 x 32 cols)
    const int n0 = blockIdx.x * 128;
    const int mb = blockIdx.y * 32;
    const uint32_t sbase = smem_u32(smem);

    const uint32_t aln = (uint32_t)(wq * 16 + 8 * (q4 & 1) + r8) * GPIT + 16 * (q4 >> 1);
    const uint32_t bln = (uint32_t)(wn * 32 + 8 * (q4 >> 1) + r8) * GPIT + 16 * (q4 & 1);

    auto load = [&](int kc, int st) {     // kc in [0,8): 64-wide k-chunk
        uint32_t b = sbase + st * GSTAGE;
        #pragma unroll
        for (int p = 0; p < 2; p++) {     // A hi (slots 0-255) / lo (256-511)
            int i = tid + p * 256;
            int r = (i & 255) >> 3, c = i & 7;
            size_t ga = ((size_t)(mb + r) * 512 + kc * 64) * 2 + c * 16;
            if (i < 256) cp16(b + GAH + r * GPIT + c * 16, (const char*)Ah + ga);
            else         cp16(b + GAL + r * GPIT + c * 16, (const char*)Al + ga);
        }
        #pragma unroll
        for (int p = 0; p < 4; p++) {     // B: 128 rows x 128B
            int i = tid + p * 256;
            int r = i >> 3, c = i & 7;
            size_t gb = ((size_t)(n0 + r) * 512 + kc * 64) * 2 + c * 16;
            cp16(b + GB + r * GPIT + c * 16, (const char*)Bt + gb);
        }
        asm volatile("cp.async.commit_group;" ::: "memory");
    };

    float acc[4][4];
    #pragma unroll
    for (int j = 0; j < 4; j++)
        #pragma unroll
        for (int i = 0; i < 4; i++) acc[j][i] = 0.0f;

    load(0, 0);
    for (int kc = 0; kc < 8; kc++) {
        if (kc + 1 < 8) {
            load(kc + 1, (kc + 1) & 1);
            asm volatile("cp.async.wait_group 1;" ::: "memory");
        } else {
            asm volatile("cp.async.wait_group 0;" ::: "memory");
        }
        __syncthreads();
        const uint32_t sb = sbase + (kc & 1) * GSTAGE;

        #pragma unroll
        for (int kk = 0; kk < 4; kk++) {
            uint32_t ah[4], al[4];
            ldsm4(ah[0], ah[1], ah[2], ah[3], sb + GAH + aln + kk * 32);
            ldsm4(al[0], al[1], al[2], al[3], sb + GAL + aln + kk * 32);
            uint32_t b0[2], b1[2], b2[2], b3[2];
            #pragma unroll
            for (int jp = 0; jp < 2; jp++)
                ldsm4(b0[jp], b1[jp], b2[jp], b3[jp],
                      sb + GB + bln + (uint32_t)jp * (16 * GPIT) + kk * 32);
            #pragma unroll
            for (int jp = 0; jp < 2; jp++) {
                mma_fp16(acc[2 * jp],     ah, b0[jp], b1[jp]);
                mma_fp16(acc[2 * jp + 1], ah, b2[jp], b3[jp]);
            }
            #pragma unroll
            for (int jp = 0; jp < 2; jp++) {
                mma_fp16(acc[2 * jp],     al, b0[jp], b1[jp]);
                mma_fp16(acc[2 * jp + 1], al, b2[jp], b3[jp]);
            }
        }
        __syncthreads();
    }

    const int r0 = mb + wq * 16 + g, r1 = r0 + 8;
    if (mode == 1) {
        #pragma unroll
        for (int j = 0; j < 4; j++) {
            int col = n0 + wn * 32 + 8 * j + 2 * t;
            float bv0 = b0p[col], bv1 = b0p[col + 1];
            *(float2*)&C_ext[(size_t)r0 * 512 + col] =
                make_float2(acc[j][0] + bv0, acc[j][1] + bv1);
            *(float2*)&C_ext[(size_t)r1 * 512 + col] =
                make_float2(acc[j][2] + bv0, acc[j][3] + bv1);
        }
    } else {
        const float QS = 0.125f * LOG2E;
        #pragma unroll
        for (int j = 0; j < 4; j++) {
            int col = n0 + wn * 32 + 8 * j + 2 * t;
            const float* bp = (col < 512) ? b0p : (col < 1024 ? b1p : b2p);
            int cc = col & 511;
            float bv0 = bp[cc], bv1 = bp[cc + 1];
            float v00 = acc[j][0] + bv0, v01 = acc[j][1] + bv1;
            float v10 = acc[j][2] + bv0, v11 = acc[j][3] + bv1;
            int h = cc >> 6, d = cc & 63;
            size_t d0 = ((size_t)h * NTOK + r0) * HDIM + d;
            size_t d1 = ((size_t)h * NTOK + r1) * HDIM + d;
            if (col < 512) {
                *(uint32_t*)&g_Qf[d0] = pack2h(v00 * QS, v01 * QS);
                *(uint32_t*)&g_Qf[d1] = pack2h(v10 * QS, v11 * QS);
            } else if (col < 1024) {
                *(uint32_t*)&g_Kf[d0] = pack2h(v00, v01);
                *(uint32_t*)&g_Kf[d1] = pack2h(v10, v11);
            } else {
                *(uint32_t*)&g_Vf[d0] = pack2h(v00, v01);
                *(uint32_t*)&g_Vf[d1] = pack2h(v10, v11);
            }
        }
    }
}

// ---------------------------------------------------------------------------
// Fused input prep:
//   blocks [0,4096): z bins | [4096,5120): W transpose (fp16) | [5120,9216): x split fp16
// ---------------------------------------------------------------------------
__device__ __forceinline__ uint8_t bin_of(float z) {
    int b = (int)floorf(z / 5.0f * 16.0f);
    return (uint8_t)max(0, min(NBINS - 1, b));
}

__global__ __launch_bounds__(256) void prep_in_kernel(
    const float* __restrict__ x, const float* __restrict__ zmat,
    const float* __restrict__ Wq, const float* __restrict__ Wk,
    const float* __restrict__ Wv, const float* __restrict__ Wo)
{
    int bx = blockIdx.x;
    int tid = threadIdx.x;
    if (bx < 4096) {
        size_t i = (size_t)bx * 256 + tid;
        float4 z = *(const float4*)(zmat + i * 4);
        uchar4 b;
        b.x = bin_of(z.x); b.y = bin_of(z.y); b.z = bin_of(z.z); b.w = bin_of(z.w);
        *(uchar4*)(g_bins + i * 4) = b;
    } else if (bx < 5120) {
        __shared__ float ts[32][33];
        int bb = bx - 4096;
        int zb = bb >> 8, rem = bb & 255;
        int k0 = (rem & 15) * 32;
        int n0 = (rem >> 4) * 32;
        const float* src;
        __half* dh;
        int nbase;
        if (zb == 0)      { src = Wq; dh = g_Wt;  nbase = 0; }
        else if (zb == 1) { src = Wk; dh = g_Wt;  nbase = 512; }
        else if (zb == 2) { src = Wv; dh = g_Wt;  nbase = 1024; }
        else              { src = Wo; dh = g_Wot; nbase = 0; }
        int tx = tid & 31, ty = tid >> 5;
        #pragma unroll
        for (int i = 0; i < 4; i++) {
            int r = ty + i * 8;
            ts[r][tx] = src[(size_t)(k0 + r) * 512 + n0 + tx];
        }
        __syncthreads();
        #pragma unroll
        for (int i = 0; i < 4; i++) {
            int nn = ty + i * 8;
            dh[(size_t)(nbase + n0 + nn) * 512 + k0 + tx] = __float2half_rn(ts[tx][nn]);
        }
    } else {
        int i = (bx - 5120) * 256 + tid;
        float v = x[i];
        __half h = __float2half_rn(v);
        g_Xh[i] = h;
        g_Xl[i] = __float2half_rn(v - __half2float(h));
    }
}

// ---------------------------------------------------------------------------
// fp16 mma.sync flash attention (validated R13): 128 q-rows, 8 warps.
// K via ldmatrix; V via ldmatrix.trans; l via FADDs.
// ---------------------------------------------------------------------------
#define KP 144
#define VP 144
#define BP 144
#define KF_O 0
#define VT_O 18432
#define BN_O 36864
#define STAGE 55296
#define ATTN_SMEM (2 * STAGE)

__global__ __launch_bounds__(256, 1) void attn_mma_kernel(const float* __restrict__ ztab)
{
    extern __shared__ char smem[];
    __shared__ float zt[NBINS];

    const int tid = threadIdx.x;
    const int w   = tid >> 5;
    const int l   = tid & 31;
    const int g   = l >> 2;
    const int t   = l & 3;
    const int q4  = l >> 3, r8 = l & 7;
    const int h   = blockIdx.y;
    const int q0  = blockIdx.x * 128;
    const int m0  = w * 16;

    if (tid < NBINS) zt[tid] = ztab[tid * NH + h] * LOG2E;

    const uint32_t sbase = smem_u32(smem);

    const uint32_t kln = (uint32_t)(8 * (q4 >> 1) + r8) * KP + 16 * (q4 & 1);
    const uint32_t vln = (uint32_t)(8 * (q4 & 1) + r8) * VP + 16 * (q4 >> 1);

    auto load_tile = [&](int kt, int stage) {
        uint32_t base = sbase + stage * STAGE;
        #pragma unroll
        for (int p = 0; p < 4; p++) {
            int i = tid + p * 256;
            int r = i >> 3, c = i & 7;
            cp16(base + KF_O + r * KP + c * 16,
                 (const char*)g_Kf + (((size_t)h * NTOK + kt * 128 + r) * HDIM) * 2 + c * 16);
        }
        #pragma unroll
        for (int p = 0; p < 4; p++) {
            int i = tid + p * 256;
            int r = i >> 3, c = i & 7;
            cp16(base + VT_O + r * VP + c * 16,
                 (const char*)g_Vf + (((size_t)h * NTOK + kt * 128 + r) * HDIM) * 2 + c * 16);
        }
        #pragma unroll
        for (int p = 0; p < 4; p++) {
            int i = tid + p * 256;
            int r = i >> 3, c = i & 7;
            cp16(base + BN_O + r * BP + c * 16,
                 g_bins + (size_t)(q0 + r) * NTOK + kt * 128 + c * 16);
        }
        asm volatile("cp.async.commit_group;" ::: "memory");
    };

    load_tile(0, 0);

    uint32_t qf[4][4];
    {
        const uint16_t* qb = (const uint16_t*)g_Qf + ((size_t)h * NTOK + q0 + m0) * HDIM;
        #pragma unroll
        for (int kk = 0; kk < 4; kk++) {
            int c0 = 16 * kk + 2 * t;
            qf[kk][0] = *(const uint32_t*)(qb + (size_t)g * HDIM + c0);
            qf[kk][1] = *(const uint32_t*)(qb + (size_t)(g + 8) * HDIM + c0);
            qf[kk][2] = *(const uint32_t*)(qb + (size_t)g * HDIM + c0 + 8);
            qf[kk][3] = *(const uint32_t*)(qb + (size_t)(g + 8) * HDIM + c0 + 8);
        }
    }

    float oc[8][4];
    #pragma unroll
    for (int j = 0; j < 8; j++)
        #pragma unroll
        for (int i = 0; i < 4; i++) oc[j][i] = 0.0f;
    float l0 = 0.0f, l1 = 0.0f;

    for (int kt = 0; kt < NTOK / 128; kt++) {
        if (kt + 1 < NTOK / 128) {
            load_tile(kt + 1, (kt + 1) & 1);
            asm volatile("cp.async.wait_group 1;" ::: "memory");
        } else {
            asm volatile("cp.async.wait_group 0;" ::: "memory");
        }
        __syncthreads();

        const uint32_t sb = sbase + (kt & 1) * STAGE;
        const char* BN = smem + (kt & 1) * STAGE + BN_O;

        float sc[16][4];
        #pragma unroll
        for (int j = 0; j < 16; j++)
            #pragma unroll
            for (int i = 0; i < 4; i++) sc[j][i] = 0.0f;

        #pragma unroll
        for (int kk = 0; kk < 4; kk++) {
            #pragma unroll
            for (int jp = 0; jp < 8; jp++) {
                uint32_t b0, b1, b2, b3;
                ldsm4(b0, b1, b2, b3, sb + KF_O + kln + (uint32_t)jp * (16 * KP) + kk * 32);
                mma_fp16(sc[2 * jp],     qf[kk], b0, b1);
                mma_fp16(sc[2 * jp + 1], qf[kk], b2, b3);
            }
        }

        uint32_t ph[8][4];
        #pragma unroll
        for (int j = 0; j < 16; j++) {
            int col = 8 * j + 2 * t;
            uint16_t bA = *(const uint16_t*)(BN + (uint32_t)(m0 + g) * BP + col);
            uint16_t bB = *(const uint16_t*)(BN + (uint32_t)(m0 + g + 8) * BP + col);
            float p0 = fast_exp2(sc[j][0] + zt[bA & 0xFF]);
            float p1 = fast_exp2(sc[j][1] + zt[bA >> 8]);
            float p2 = fast_exp2(sc[j][2] + zt[bB & 0xFF]);
            float p3 = fast_exp2(sc[j][3] + zt[bB >> 8]);
            l0 += p0 + p1;
            l1 += p2 + p3;
            int kp = j >> 1, hf = (j & 1) * 2;
            ph[kp][hf + 0] = pack2h(p0, p1);
            ph[kp][hf + 1] = pack2h(p2, p3);
        }

        #pragma unroll
        for (int kp = 0; kp < 8; kp++) {
            #pragma unroll
            for (int jjp = 0; jjp < 2; jjp++) {
                uint32_t v0, v1, v2, v3;
                ldsm4t(v0, v1, v2, v3,
                       sb + VT_O + vln + (uint32_t)kp * (16 * VP) + jjp * 32);
                mma_fp16(oc[4 * jjp + 0], ph[kp], v0, v1);
                mma_fp16(oc[4 * jjp + 1], ph[kp], v2, v3);
            }
            #pragma unroll
            for (int jjp = 0; jjp < 2; jjp++) {
                uint32_t v0, v1, v2, v3;
                ldsm4t(v0, v1, v2, v3,
                       sb + VT_O + vln + (uint32_t)kp * (16 * VP) + 64 + jjp * 32);
                mma_fp16(oc[4 * jjp + 2], ph[kp], v0, v1);
                mma_fp16(oc[4 * jjp + 3], ph[kp], v2, v3);
            }
        }
        __syncthreads();
    }

    l0 += __shfl_xor_sync(0xffffffffu, l0, 1);
    l0 += __shfl_xor_sync(0xffffffffu, l0, 2);
    l1 += __shfl_xor_sync(0xffffffffu, l1, 1);
    l1 += __shfl_xor_sync(0xffffffffu, l1, 2);
    float inv0 = 1.0f / l0, inv1 = 1.0f / l1;

    const int dmap[8] = {0, 8, 32, 40, 16, 24, 48, 56};

    int r0 = q0 + m0 + g, r1 = r0 + 8;
    #pragma unroll
    for (int jj = 0; jj < 8; jj++) {
        int col = h * HDIM + dmap[jj] + 2 * t;
        float v00 = oc[jj][0] * inv0, v01 = oc[jj][1] * inv0;
        float v10 = oc[jj][2] * inv1, v11 = oc[jj][3] * inv1;
        __half h00 = __float2half_rn(v00);
        __half h01 = __float2half_rn(v01);
        __half h10 = __float2half_rn(v10);
        __half h11 = __float2half_rn(v11);
        __half2 u0; u0.x = h00; u0.y = h01;
        __half2 u1; u1.x = h10; u1.y = h11;
        *(uint32_t*)&g_AOh[(size_t)r0 * DMOD + col] = *(uint32_t*)&u0;
        *(uint32_t*)&g_AOh[(size_t)r1 * DMOD + col] = *(uint32_t*)&u1;
        *(uint32_t*)&g_AOl[(size_t)r0 * DMOD + col] =
            pack2h(v00 - __half2float(h00), v01 - __half2float(h01));
        *(uint32_t*)&g_AOl[(size_t)r1 * DMOD + col] =
            pack2h(v10 - __half2float(h10), v11 - __half2float(h11));
    }
}

// ---------------------------------------------------------------------------

extern "C" void kernel_launch(void* const* d_in, const int* in_sizes, int n_in,
                              void* d_out, int out_size)
{
    const float* x  = (const float*)d_in[0];
    const float* z  = (const float*)d_in[1];
    const float* Wq = (const float*)d_in[2];
    const float* bq = (const float*)d_in[3];
    const float* Wk = (const float*)d_in[4];
    const float* bk = (const float*)d_in[5];
    const float* Wv = (const float*)d_in[6];
    const float* bv = (const float*)d_in[7];
    const float* Wo = (const float*)d_in[8];
    const float* bo = (const float*)d_in[9];
    const float* zt = (const float*)d_in[10];
    float* out = (float*)d_out;

    cudaFuncSetAttribute(attn_mma_kernel,
                         cudaFuncAttributeMaxDynamicSharedMemorySize, ATTN_SMEM);
    cudaFuncSetAttribute(gemm_mma_kernel,
                         cudaFuncAttributeMaxDynamicSharedMemorySize, GEMM_SMEM);

    // fused prep: bins + W transpose (fp16) + x split (fp16)
    prep_in_kernel<<<9216, 256>>>(x, z, Wq, Wk, Wv, Wo);

    // fused QKV projection (2-term fp16, 32x128 tiles, k-chunk 64)
    gemm_mma_kernel<<<dim3(12, 64), 256, GEMM_SMEM>>>(0, bq, bk, bv, nullptr);

    // attention (V via ldmatrix.trans)
    attn_mma_kernel<<<dim3(NTOK / 128, NH), 256, ATTN_SMEM>>>(zt);

    // output projection (32x128 tiles, k-chunk 64)
    gemm_mma_kernel<<<dim3(4, 64), 256, GEMM_SMEM>>>(1, bo, nullptr, nullptr, out);
}

// round 16
// speedup vs baseline: 1.0777x; 1.0076x over previous
#include <cuda_runtime.h>
#include <cuda_fp16.h>
#include <math.h>
#include <stdint.h>

#define NTOK 2048
#define DMOD 512
#define NH 8
#define HDIM 64
#define NBINS 16

// ---------------------------------------------------------------------------
// Scratch (no cudaMalloc). Only referenced from DEVICE code.
// ---------------------------------------------------------------------------
__device__ __half g_Xh[NTOK * DMOD], g_Xl[NTOK * DMOD];    // split x (fp16 hi/lo)
__device__ __half g_Wt[1536 * 512];                        // (Wq|Wk|Wv)^T fp16
__device__ __half g_Wot[512 * 512];                        // Wo^T fp16
__device__ __half g_AOh[NTOK * DMOD], g_AOl[NTOK * DMOD];  // attn out split fp16
__device__ __half g_Qf[NTOK * DMOD];                       // [h][tok][64] fp16
__device__ __half g_Kf[NTOK * DMOD];                       // [h][tok][64] fp16
__device__ __half g_Vf[NTOK * DMOD];                       // [h][tok][64] fp16
__device__ uint8_t g_bins[NTOK * NTOK];

#define LOG2E 1.4426950408889634f

// ---------------------------------------------------------------------------
// mma.sync / cp.async / ldmatrix helpers
// ---------------------------------------------------------------------------
__device__ __forceinline__ void mma_fp16(float* c, const uint32_t* a,
                                         uint32_t b0, uint32_t b1) {
    asm volatile(
        "mma.sync.aligned.m16n8k16.row.col.f32.f16.f16.f32 "
        "{%0,%1,%2,%3},{%4,%5,%6,%7},{%8,%9},{%0,%1,%2,%3};"
        : "+f"(c[0]), "+f"(c[1]), "+f"(c[2]), "+f"(c[3])
        : "r"(a[0]), "r"(a[1]), "r"(a[2]), "r"(a[3]), "r"(b0), "r"(b1));
}
__device__ __forceinline__ void ldsm4(uint32_t& r0, uint32_t& r1,
                                      uint32_t& r2, uint32_t& r3, uint32_t addr) {
    asm volatile("ldmatrix.sync.aligned.m8n8.x4.shared.b16 {%0,%1,%2,%3}, [%4];"
                 : "=r"(r0), "=r"(r1), "=r"(r2), "=r"(r3) : "r"(addr));
}
__device__ __forceinline__ void ldsm4t(uint32_t& r0, uint32_t& r1,
                                       uint32_t& r2, uint32_t& r3, uint32_t addr) {
    asm volatile("ldmatrix.sync.aligned.m8n8.x4.trans.shared.b16 {%0,%1,%2,%3}, [%4];"
                 : "=r"(r0), "=r"(r1), "=r"(r2), "=r"(r3) : "r"(addr));
}
__device__ __forceinline__ void cp16(uint32_t dst, const void* src) {
    asm volatile("cp.async.cg.shared.global [%0], [%1], 16;" :: "r"(dst), "l"(src));
}
__device__ __forceinline__ uint32_t smem_u32(const void* p) {
    uint32_t a;
    asm("{ .reg .u64 t; cvta.to.shared.u64 t, %1; cvt.u32.u64 %0, t; }"
        : "=r"(a) : "l"(p));
    return a;
}
__device__ __forceinline__ uint32_t pack2h(float a, float b) {
    __half2 t;
    t.x = __float2half_rn(a);
    t.y = __float2half_rn(b);
    return *(uint32_t*)&t;
}
__device__ __forceinline__ float fast_exp2(float x) {
    float r;
    asm("ex2.approx.ftz.f32 %0, %1;" : "=f"(r) : "f"(x));
    return r;
}

// ---------------------------------------------------------------------------
// 2-term split-fp16 tensor-core GEMM, 32x128 tiles, k-chunk 64,
// 3-stage circular cp.async pipeline, ONE sync per k-iteration.
// mode 0: QKV (grid 12x64 = 768 CTAs); mode 1: outproj (grid 4x64 = 256 CTAs).
// ---------------------------------------------------------------------------
#define GPIT 144
#define GAH 0
#define GAL 4608
#define GB  9216
#define GSTAGE 27648
#define GEMM_SMEM (3 * GSTAGE)

__global__ __launch_bounds__(256, 2) void gemm_mma_kernel(
    int mode, const float* __restrict__ b0p, const float* __restrict__ b1p,
    const float* __restrict__ b2p, float* __restrict__ C_ext)
{
    extern __shared__ char smem[];
    const __half *Ah, *Al, *Bt;
    if (mode == 0) {
        Ah = g_Xh;  Al = g_Xl;  Bt = g_Wt;
    } else {
        Ah = g_AOh; Al = g_AOl; Bt = g_Wot;
    }

    const int tid = threadIdx.x;
    const int w = tid >> 5, l = tid & 31, g = l >> 2, t = l & 3;
    const int q4 = l >> 3, r8 = l & 7;
    const int wq = w & 1;          // M row-group (2 x 16 rows)
    const int wn = w >> 1;         // N quarter (4 x 32 cols)
    const int n0 = blockIdx.x * 128;
    const int mb = blockIdx.y * 32;
    const uint32_t sbase = smem_u32(smem);

    const uint32_t aln = (uint32_t)(wq * 16 + 8 * (q4 & 1) + r8) * GPIT + 16 * (q4 >> 1);
    const uint32_t bln = (uint32_t)(wn * 32 + 8 * (q4 >> 1) + r8) * GPIT + 16 * (q4 & 1);

    auto load = [&](int kc, int st) {     // kc in [0,8): 64-wide k-chunk
        uint32_t b = sbase + st * GSTAGE;
        #pragma unroll
        for (int p = 0; p < 2; p++) {     // A hi (slots 0-255) / lo (256-511)
            int i = tid + p * 256;
            int r = (i & 255) >> 3, c = i & 7;
            size_t ga = ((size_t)(mb + r) * 512 + kc * 64) * 2 + c * 16;
            if (i < 256) cp16(b + GAH + r * GPIT + c * 16, (const char*)Ah + ga);
            else         cp16(b + GAL + r * GPIT + c * 16, (const char*)Al + ga);
        }
        #pragma unroll
        for (int p = 0; p < 4; p++) {     // B: 128 rows x 128B
            int i = tid + p * 256;
            int r = i >> 3, c = i & 7;
            size_t gb = ((size_t)(n0 + r) * 512 + kc * 64) * 2 + c * 16;
            cp16(b + GB + r * GPIT + c * 16, (const char*)Bt + gb);
        }
        asm volatile("cp.async.commit_group;" ::: "memory");
    };

    float acc[4][4];
    #pragma unroll
    for (int j = 0; j < 4; j++)
        #pragma unroll
        for (int i = 0; i < 4; i++) acc[j][i] = 0.0f;

    load(0, 0);
    load(1, 1);
    for (int kc = 0; kc < 8; kc++) {
        if (kc < 7) {
            asm volatile("cp.async.wait_group 1;" ::: "memory");
        } else {
            asm volatile("cp.async.wait_group 0;" ::: "memory");
        }
        __syncthreads();
        if (kc + 2 < 8) load(kc + 2, (kc + 2) % 3);

        const uint32_t sb = sbase + (kc % 3) * GSTAGE;
        #pragma unroll
        for (int kk = 0; kk < 4; kk++) {
            uint32_t ah[4], al[4];
            ldsm4(ah[0], ah[1], ah[2], ah[3], sb + GAH + aln + kk * 32);
            ldsm4(al[0], al[1], al[2], al[3], sb + GAL + aln + kk * 32);
            uint32_t b0[2], b1[2], b2[2], b3[2];
            #pragma unroll
            for (int jp = 0; jp < 2; jp++)
                ldsm4(b0[jp], b1[jp], b2[jp], b3[jp],
                      sb + GB + bln + (uint32_t)jp * (16 * GPIT) + kk * 32);
            #pragma unroll
            for (int jp = 0; jp < 2; jp++) {
                mma_fp16(acc[2 * jp],     ah, b0[jp], b1[jp]);
                mma_fp16(acc[2 * jp + 1], ah, b2[jp], b3[jp]);
            }
            #pragma unroll
            for (int jp = 0; jp < 2; jp++) {
                mma_fp16(acc[2 * jp],     al, b0[jp], b1[jp]);
                mma_fp16(acc[2 * jp + 1], al, b2[jp], b3[jp]);
            }
        }
    }

    const int r0 = mb + wq * 16 + g, r1 = r0 + 8;
    if (mode == 1) {
        #pragma unroll
        for (int j = 0; j < 4; j++) {
            int col = n0 + wn * 32 + 8 * j + 2 * t;
            float bv0 = b0p[col], bv1 = b0p[col + 1];
            *(float2*)&C_ext[(size_t)r0 * 512 + col] =
                make_float2(acc[j][0] + bv0, acc[j][1] + bv1);
            *(float2*)&C_ext[(size_t)r1 * 512 + col] =
                make_float2(acc[j][2] + bv0, acc[j][3] + bv1);
        }
    } else {
        const float QS = 0.125f * LOG2E;
        #pragma unroll
        for (int j = 0; j < 4; j++) {
            int col = n0 + wn * 32 + 8 * j + 2 * t;
            const float* bp = (col < 512) ? b0p : (col < 1024 ? b1p : b2p);
            int cc = col & 511;
            float bv0 = bp[cc], bv1 = bp[cc + 1];
            float v00 = acc[j][0] + bv0, v01 = acc[j][1] + bv1;
            float v10 = acc[j][2] + bv0, v11 = acc[j][3] + bv1;
            int h = cc >> 6, d = cc & 63;
            size_t d0 = ((size_t)h * NTOK + r0) * HDIM + d;
            size_t d1 = ((size_t)h * NTOK + r1) * HDIM + d;
            if (col < 512) {
                *(uint32_t*)&g_Qf[d0] = pack2h(v00 * QS, v01 * QS);
                *(uint32_t*)&g_Qf[d1] = pack2h(v10 * QS, v11 * QS);
            } else if (col < 1024) {
                *(uint32_t*)&g_Kf[d0] = pack2h(v00, v01);
                *(uint32_t*)&g_Kf[d1] = pack2h(v10, v11);
            } else {
                *(uint32_t*)&g_Vf[d0] = pack2h(v00, v01);
                *(uint32_t*)&g_Vf[d1] = pack2h(v10, v11);
            }
        }
    }
}

// ---------------------------------------------------------------------------
// Fused input prep:
//   blocks [0,4096): z bins | [4096,5120): W transpose (fp16) | [5120,9216): x split fp16
// ---------------------------------------------------------------------------
__device__ __forceinline__ uint8_t bin_of(float z) {
    int b = (int)floorf(z / 5.0f * 16.0f);
    return (uint8_t)max(0, min(NBINS - 1, b));
}

__global__ __launch_bounds__(256) void prep_in_kernel(
    const float* __restrict__ x, const float* __restrict__ zmat,
    const float* __restrict__ Wq, const float* __restrict__ Wk,
    const float* __restrict__ Wv, const float* __restrict__ Wo)
{
    int bx = blockIdx.x;
    int tid = threadIdx.x;
    if (bx < 4096) {
        size_t i = (size_t)bx * 256 + tid;
        float4 z = *(const float4*)(zmat + i * 4);
        uchar4 b;
        b.x = bin_of(z.x); b.y = bin_of(z.y); b.z = bin_of(z.z); b.w = bin_of(z.w);
        *(uchar4*)(g_bins + i * 4) = b;
    } else if (bx < 5120) {
        __shared__ float ts[32][33];
        int bb = bx - 4096;
        int zb = bb >> 8, rem = bb & 255;
        int k0 = (rem & 15) * 32;
        int n0 = (rem >> 4) * 32;
        const float* src;
        __half* dh;
        int nbase;
        if (zb == 0)      { src = Wq; dh = g_Wt;  nbase = 0; }
        else if (zb == 1) { src = Wk; dh = g_Wt;  nbase = 512; }
        else if (zb == 2) { src = Wv; dh = g_Wt;  nbase = 1024; }
        else              { src = Wo; dh = g_Wot; nbase = 0; }
        int tx = tid & 31, ty = tid >> 5;
        #pragma unroll
        for (int i = 0; i < 4; i++) {
            int r = ty + i * 8;
            ts[r][tx] = src[(size_t)(k0 + r) * 512 + n0 + tx];
        }
        __syncthreads();
        #pragma unroll
        for (int i = 0; i < 4; i++) {
            int nn = ty + i * 8;
            dh[(size_t)(nbase + n0 + nn) * 512 + k0 + tx] = __float2half_rn(ts[tx][nn]);
        }
    } else {
        int i = (bx - 5120) * 256 + tid;
        float v = x[i];
        __half h = __float2half_rn(v);
        g_Xh[i] = h;
        g_Xl[i] = __float2half_rn(v - __half2float(h));
    }
}

// ---------------------------------------------------------------------------
// fp16 mma.sync flash attention: 128 q-rows, 8 warps, 3-stage cp.async
// pipeline with one sync per key-tile. K via ldmatrix; V via ldmatrix.trans;
// l via FADDs.
// ---------------------------------------------------------------------------
#define KP 144
#define VP 144
#define BP 144
#define KF_O 0
#define VT_O 18432
#define BN_O 36864
#define STAGE 55296
#define ATTN_SMEM (3 * STAGE)
#define NKT (NTOK / 128)

__global__ __launch_bounds__(256, 1) void attn_mma_kernel(const float* __restrict__ ztab)
{
    extern __shared__ char smem[];
    __shared__ float zt[NBINS];

    const int tid = threadIdx.x;
    const int w   = tid >> 5;
    const int l   = tid & 31;
    const int g   = l >> 2;
    const int t   = l & 3;
    const int q4  = l >> 3, r8 = l & 7;
    const int h   = blockIdx.y;
    const int q0  = blockIdx.x * 128;
    const int m0  = w * 16;

    if (tid < NBINS) zt[tid] = ztab[tid * NH + h] * LOG2E;

    const uint32_t sbase = smem_u32(smem);

    const uint32_t kln = (uint32_t)(8 * (q4 >> 1) + r8) * KP + 16 * (q4 & 1);
    const uint32_t vln = (uint32_t)(8 * (q4 & 1) + r8) * VP + 16 * (q4 >> 1);

    auto load_tile = [&](int kt, int stage) {
        uint32_t base = sbase + stage * STAGE;
        #pragma unroll
        for (int p = 0; p < 4; p++) {
            int i = tid + p * 256;
            int r = i >> 3, c = i & 7;
            cp16(base + KF_O + r * KP + c * 16,
                 (const char*)g_Kf + (((size_t)h * NTOK + kt * 128 + r) * HDIM) * 2 + c * 16);
        }
        #pragma unroll
        for (int p = 0; p < 4; p++) {
            int i = tid + p * 256;
            int r = i >> 3, c = i & 7;
            cp16(base + VT_O + r * VP + c * 16,
                 (const char*)g_Vf + (((size_t)h * NTOK + kt * 128 + r) * HDIM) * 2 + c * 16);
        }
        #pragma unroll
        for (int p = 0; p < 4; p++) {
            int i = tid + p * 256;
            int r = i >> 3, c = i & 7;
            cp16(base + BN_O + r * BP + c * 16,
                 g_bins + (size_t)(q0 + r) * NTOK + kt * 128 + c * 16);
        }
        asm volatile("cp.async.commit_group;" ::: "memory");
    };

    load_tile(0, 0);
    load_tile(1, 1);

    uint32_t qf[4][4];
    {
        const uint16_t* qb = (const uint16_t*)g_Qf + ((size_t)h * NTOK + q0 + m0) * HDIM;
        #pragma unroll
        for (int kk = 0; kk < 4; kk++) {
            int c0 = 16 * kk + 2 * t;
            qf[kk][0] = *(const uint32_t*)(qb + (size_t)g * HDIM + c0);
            qf[kk][1] = *(const uint32_t*)(qb + (size_t)(g + 8) * HDIM + c0);
            qf[kk][2] = *(const uint32_t*)(qb + (size_t)g * HDIM + c0 + 8);
            qf[kk][3] = *(const uint32_t*)(qb + (size_t)(g + 8) * HDIM + c0 + 8);
        }
    }

    float oc[8][4];
    #pragma unroll
    for (int j = 0; j < 8; j++)
        #pragma unroll
        for (int i = 0; i < 4; i++) oc[j][i] = 0.0f;
    float l0 = 0.0f, l1 = 0.0f;

    for (int kt = 0; kt < NKT; kt++) {
        if (kt < NKT - 1) {
            asm volatile("cp.async.wait_group 1;" ::: "memory");
        } else {
            asm volatile("cp.async.wait_group 0;" ::: "memory");
        }
        __syncthreads();
        if (kt + 2 < NKT) load_tile(kt + 2, (kt + 2) % 3);

        const uint32_t sb = sbase + (kt % 3) * STAGE;
        const char* BN = smem + (kt % 3) * STAGE + BN_O;

        float sc[16][4];
        #pragma unroll
        for (int j = 0; j < 16; j++)
            #pragma unroll
            for (int i = 0; i < 4; i++) sc[j][i] = 0.0f;

        #pragma unroll
        for (int kk = 0; kk < 4; kk++) {
            #pragma unroll
            for (int jp = 0; jp < 8; jp++) {
                uint32_t b0, b1, b2, b3;
                ldsm4(b0, b1, b2, b3, sb + KF_O + kln + (uint32_t)jp * (16 * KP) + kk * 32);
                mma_fp16(sc[2 * jp],     qf[kk], b0, b1);
                mma_fp16(sc[2 * jp + 1], qf[kk], b2, b3);
            }
        }

        uint32_t ph[8][4];
        #pragma unroll
        for (int j = 0; j < 16; j++) {
            int col = 8 * j + 2 * t;
            uint16_t bA = *(const uint16_t*)(BN + (uint32_t)(m0 + g) * BP + col);
            uint16_t bB = *(const uint16_t*)(BN + (uint32_t)(m0 + g + 8) * BP + col);
            float p0 = fast_exp2(sc[j][0] + zt[bA & 0xFF]);
            float p1 = fast_exp2(sc[j][1] + zt[bA >> 8]);
            float p2 = fast_exp2(sc[j][2] + zt[bB & 0xFF]);
            float p3 = fast_exp2(sc[j][3] + zt[bB >> 8]);
            l0 += p0 + p1;
            l1 += p2 + p3;
            int kp = j >> 1, hf = (j & 1) * 2;
            ph[kp][hf + 0] = pack2h(p0, p1);
            ph[kp][hf + 1] = pack2h(p2, p3);
        }

        #pragma unroll
        for (int kp = 0; kp < 8; kp++) {
            #pragma unroll
            for (int jjp = 0; jjp < 2; jjp++) {
                uint32_t v0, v1, v2, v3;
                ldsm4t(v0, v1, v2, v3,
                       sb + VT_O + vln + (uint32_t)kp * (16 * VP) + jjp * 32);
                mma_fp16(oc[4 * jjp + 0], ph[kp], v0, v1);
                mma_fp16(oc[4 * jjp + 1], ph[kp], v2, v3);
            }
            #pragma unroll
            for (int jjp = 0; jjp < 2; jjp++) {
                uint32_t v0, v1, v2, v3;
                ldsm4t(v0, v1, v2, v3,
                       sb + VT_O + vln + (uint32_t)kp * (16 * VP) + 64 + jjp * 32);
                mma_fp16(oc[4 * jjp + 2], ph[kp], v0, v1);
                mma_fp16(oc[4 * jjp + 3], ph[kp], v2, v3);
            }
        }
    }

    l0 += __shfl_xor_sync(0xffffffffu, l0, 1);
    l0 += __shfl_xor_sync(0xffffffffu, l0, 2);
    l1 += __shfl_xor_sync(0xffffffffu, l1, 1);
    l1 += __shfl_xor_sync(0xffffffffu, l1, 2);
    float inv0 = 1.0f / l0, inv1 = 1.0f / l1;

    const int dmap[8] = {0, 8, 32, 40, 16, 24, 48, 56};

    int r0 = q0 + m0 + g, r1 = r0 + 8;
    #pragma unroll
    for (int jj = 0; jj < 8; jj++) {
        int col = h * HDIM + dmap[jj] + 2 * t;
        float v00 = oc[jj][0] * inv0, v01 = oc[jj][1] * inv0;
        float v10 = oc[jj][2] * inv1, v11 = oc[jj][3] * inv1;
        __half h00 = __float2half_rn(v00);
        __half h01 = __float2half_rn(v01);
        __half h10 = __float2half_rn(v10);
        __half h11 = __float2half_rn(v11);
        __half2 u0; u0.x = h00; u0.y = h01;
        __half2 u1; u1.x = h10; u1.y = h11;
        *(uint32_t*)&g_AOh[(size_t)r0 * DMOD + col] = *(uint32_t*)&u0;
        *(uint32_t*)&g_AOh[(size_t)r1 * DMOD + col] = *(uint32_t*)&u1;
        *(uint32_t*)&g_AOl[(size_t)r0 * DMOD + col] =
            pack2h(v00 - __half2float(h00), v01 - __half2float(h01));
        *(uint32_t*)&g_AOl[(size_t)r1 * DMOD + col] =
            pack2h(v10 - __half2float(h10), v11 - __half2float(h11));
    }
}

// ---------------------------------------------------------------------------

extern "C" void kernel_launch(void* const* d_in, const int* in_sizes, int n_in,
                              void* d_out, int out_size)
{
    const float* x  = (const float*)d_in[0];
    const float* z  = (const float*)d_in[1];
    const float* Wq = (const float*)d_in[2];
    const float* bq = (const float*)d_in[3];
    const float* Wk = (const float*)d_in[4];
    const float* bk = (const float*)d_in[5];
    const float* Wv = (const float*)d_in[6];
    const float* bv = (const float*)d_in[7];
    const float* Wo = (const float*)d_in[8];
    const float* bo = (const float*)d_in[9];
    const float* zt = (const float*)d_in[10];
    float* out = (float*)d_out;

    cudaFuncSetAttribute(attn_mma_kernel,
                         cudaFuncAttributeMaxDynamicSharedMemorySize, ATTN_SMEM);
    cudaFuncSetAttribute(gemm_mma_kernel,
                         cudaFuncAttributeMaxDynamicSharedMemorySize, GEMM_SMEM);

    // fused prep: bins + W transpose (fp16) + x split (fp16)
    prep_in_kernel<<<9216, 256>>>(x, z, Wq, Wk, Wv, Wo);

    // fused QKV projection (2-term fp16, 32x128 tiles, k-chunk 64, 3-stage)
    gemm_mma_kernel<<<dim3(12, 64), 256, GEMM_SMEM>>>(0, bq, bk, bv, nullptr);

    // attention (3-stage pipeline, V via ldmatrix.trans)
    attn_mma_kernel<<<dim3(NTOK / 128, NH), 256, ATTN_SMEM>>>(zt);

    // output projection (32x128 tiles, k-chunk 64, 3-stage)
    gemm_mma_kernel<<<dim3(4, 64), 256, GEMM_SMEM>>>(1, bo, nullptr, nullptr, out);
}